// round 15
// baseline (speedup 1.0000x reference)
#include <cuda_runtime.h>
#include <cuda_bf16.h>
#include <cuda_fp16.h>
#include <mma.h>
#include <math.h>
#include <cstdint>

using namespace nvcuda;
typedef __nv_bfloat16 bf16;

#define SEQ   2048
#define DMOD  1024
#define NHEAD 16
#define HDIM  64
#define DMLP  8192

// ---------------- scratch -----------------------------------------------------
__device__ float  g_h   [SEQ * DMOD];
__device__ __half g_xn16 [SEQ * DMOD];
__device__ __half g_at16 [SEQ * DMOD];
__device__ __half g_hn16 [SEQ * DMOD];
__device__ __half g_mlp16[SEQ * (DMLP / 2)];
__device__ __half g_Wa16[3 * DMOD * DMOD];
__device__ __half g_Wo16[DMOD * DMOD];
__device__ __half g_Wp16[DMLP * DMOD];
__device__ __half g_Wf16[DMOD * DMLP / 2];
// head-major RoPE'd q/k (bf16 hi/lo) and v (fp16):  [h][l][64]
__device__ bf16   g_qh[SEQ * DMOD], g_ql[SEQ * DMOD];
__device__ bf16   g_kh[SEQ * DMOD], g_kl[SEQ * DMOD];
__device__ __half g_v16[SEQ * DMOD];

__device__ __forceinline__ void split_hl(float v, bf16& h, bf16& l) {
    h = __float2bfloat16(v);
    l = __float2bfloat16(v - __bfloat162float(h));
}
__device__ __forceinline__ void cp16b(bf16* dst, const bf16* src) {
    uint32_t s = (uint32_t)__cvta_generic_to_shared(dst);
    asm volatile("cp.async.cg.shared.global [%0], [%1], 16;\n" :: "r"(s), "l"(src));
}
__device__ __forceinline__ void cp16h(__half* dst, const __half* src) {
    uint32_t s = (uint32_t)__cvta_generic_to_shared(dst);
    asm volatile("cp.async.cg.shared.global [%0], [%1], 16;\n" :: "r"(s), "l"(src));
}

// ---------------- fused fp32 -> fp16 convert for all 4 weights -----------------
__global__ void __launch_bounds__(256) cvt_all(
    const float* __restrict__ s0, __half* __restrict__ d0, int n0,
    const float* __restrict__ s1, __half* __restrict__ d1, int n1,
    const float* __restrict__ s2, __half* __restrict__ d2, int n2,
    const float* __restrict__ s3, __half* __restrict__ d3, int n3)
{
    long i = ((long)blockIdx.x * 256 + threadIdx.x) * 8;
    const float* s; __half* d; long off = i;
    if (off < n0)              { s = s0; d = d0; }
    else if ((off -= n0) < n1) { s = s1; d = d1; }
    else if ((off -= n1) < n2) { s = s2; d = d2; }
    else if ((off -= n2) < n3) { s = s3; d = d3; }
    else return;
    float4 v0 = *(const float4*)(s + off);
    float4 v1 = *(const float4*)(s + off + 4);
    float a[8] = {v0.x, v0.y, v0.z, v0.w, v1.x, v1.y, v1.z, v1.w};
    __align__(16) __half hh[8];
    #pragma unroll
    for (int e = 0; e < 8; e++) hh[e] = __float2half_rn(a[e]);
    *(uint4*)(d + off) = *(uint4*)hh;
}

// ---------------- LayerNorm -> fp16 ---------------------------------------------
__global__ void __launch_bounds__(256) ln_kernel(const float* __restrict__ x,
                                                 __half* __restrict__ y) {
    __shared__ float row[DMOD];
    __shared__ float red[256];
    const int r   = blockIdx.x;
    const int tid = threadIdx.x;
    const float* xr = x + (long)r * DMOD;

    float s = 0.f;
    #pragma unroll
    for (int i = 0; i < 4; i++) {
        float v = xr[tid + i * 256];
        row[tid + i * 256] = v;
        s += v;
    }
    red[tid] = s; __syncthreads();
    #pragma unroll
    for (int off = 128; off > 0; off >>= 1) {
        if (tid < off) red[tid] += red[tid + off];
        __syncthreads();
    }
    const float mu = red[0] * (1.f / DMOD);
    __syncthreads();

    float ss = 0.f;
    #pragma unroll
    for (int i = 0; i < 4; i++) {
        float d = row[tid + i * 256] - mu;
        ss += d * d;
    }
    red[tid] = ss; __syncthreads();
    #pragma unroll
    for (int off = 128; off > 0; off >>= 1) {
        if (tid < off) red[tid] += red[tid + off];
        __syncthreads();
    }
    const float inv = rsqrtf(red[0] * (1.f / DMOD) + 1e-5f);

    __half* yr = y + (long)r * DMOD;
    #pragma unroll
    for (int i = 0; i < 4; i++) {
        int c = tid + i * 256;
        yr[c] = __float2half_rn((row[c] - mu) * inv);
    }
}

// ---------------- common GEMM pieces --------------------------------------------
#define GBK   32
#define PADK  40
#define CSTR  132
#define GH_SMEM   (2 * 2 * 128 * PADK * (int)sizeof(__half))   // 40960 B
#define GEP_SMEM  (128 * CSTR * (int)sizeof(float))            // 67584 B

#define GEMM_PROLOG_BODY                                                        \
    const int tid  = threadIdx.x;                                               \
    const int m0   = blockIdx.y * 128;                                          \
    const int n0   = blockIdx.x * 128;                                          \
    const int warp = tid >> 5;                                                  \
    const int wm0  = (warp & 3) * 32;                                           \
    const int wn0  = (warp >> 2) * 64;

#define GH_LOAD(ST, K0)                                                        \
do {                                                                           \
    __half* sb = smh + (ST) * (2 * 128 * PADK);                                \
    _Pragma("unroll")                                                          \
    for (int t = 0; t < 4; t++) {                                              \
        int c   = tid + t * 256;                                               \
        int arr = c >> 9;                                                      \
        int rem = c & 511;                                                     \
        int row = rem >> 2;                                                    \
        int col = (rem & 3) * 8;                                               \
        const __half* src = arr ? Bbase + (long)row * ldb + (K0) + col         \
                                : Abase + (long)row * lda + (K0) + col;        \
        cp16h(sb + arr * (128 * PADK) + row * PADK + col, src);                \
    }                                                                          \
    asm volatile("cp.async.commit_group;\n" ::);                               \
} while (0)

#define GEMM_MAINLOOP                                                           \
    const int nk = K / GBK;                                                     \
    GH_LOAD(0, 0);                                                              \
    for (int ks = 0; ks < nk; ks++) {                                           \
        asm volatile("cp.async.wait_group 0;\n" ::);                            \
        __syncthreads();                                                        \
        if (ks + 1 < nk) GH_LOAD((ks + 1) & 1, (ks + 1) * GBK);                 \
        __half* sb = smh + (ks & 1) * (2 * 128 * PADK);                         \
        __half* sA = sb;                                                        \
        __half* sB = sb + 128 * PADK;                                           \
        _Pragma("unroll")                                                       \
        for (int k16 = 0; k16 < GBK; k16 += 16) {                               \
            wmma::fragment<wmma::matrix_a, 16, 16, 16, __half,                  \
                           wmma::row_major> af[2];                              \
            _Pragma("unroll")                                                   \
            for (int i = 0; i < 2; i++)                                         \
                wmma::load_matrix_sync(af[i],                                   \
                    sA + (wm0 + 16 * i) * PADK + k16, PADK);                    \
            _Pragma("unroll")                                                   \
            for (int j = 0; j < 4; j++) {                                       \
                wmma::fragment<wmma::matrix_b, 16, 16, 16, __half,              \
                               wmma::col_major> bfr;                            \
                wmma::load_matrix_sync(bfr,                                     \
                    sB + (wn0 + 16 * j) * PADK + k16, PADK);                    \
                _Pragma("unroll")                                               \
                for (int i = 0; i < 2; i++)                                     \
                    wmma::mma_sync(acc[i][j], af[i], bfr, acc[i][j]);           \
            }                                                                   \
        }                                                                       \
    }

// ---------------- GEMM -> fp32 C (+Res) ------------------------------------------
__global__ void __launch_bounds__(256, 2) gemm_h(
    const __half* __restrict__ A, int lda,
    const __half* __restrict__ B, int ldb,
    float* __restrict__ C, int ldc, const float* __restrict__ Res, int K)
{
    extern __shared__ __half smh[];
    GEMM_PROLOG_BODY
    wmma::fragment<wmma::accumulator, 16, 16, 16, float> acc[2][4];
    #pragma unroll
    for (int i = 0; i < 2; i++)
        #pragma unroll
        for (int j = 0; j < 4; j++) {
            if (Res) {
                const float* rp = Res + (long)(m0 + wm0 + 16 * i) * ldc
                                      + n0 + wn0 + 16 * j;
                wmma::load_matrix_sync(acc[i][j], rp, ldc, wmma::mem_row_major);
            } else {
                wmma::fill_fragment(acc[i][j], 0.f);
            }
        }
    const __half* Abase = A + (long)m0 * lda;
    const __half* Bbase = B + (long)n0 * ldb;
    GEMM_MAINLOOP
    #pragma unroll
    for (int i = 0; i < 2; i++)
        #pragma unroll
        for (int j = 0; j < 4; j++) {
            float* cp = C + (long)(m0 + wm0 + 16 * i) * ldc + n0 + wn0 + 16 * j;
            wmma::store_matrix_sync(cp, acc[i][j], ldc, wmma::mem_row_major);
        }
}

// ---------------- QKV GEMM with fused RoPE + head-major split --------------------
// Each 128-col tile is entirely q, k, or v (1024-col sections, head = 64 cols).
__global__ void __launch_bounds__(256, 2) gemm_qkv_rope(
    const __half* __restrict__ A, int lda,
    const __half* __restrict__ B, int ldb, int K,
    bf16* __restrict__ qh, bf16* __restrict__ ql,
    bf16* __restrict__ kh, bf16* __restrict__ kl,
    __half* __restrict__ v16)
{
    extern __shared__ __half smh[];
    GEMM_PROLOG_BODY
    wmma::fragment<wmma::accumulator, 16, 16, 16, float> acc[2][4];
    #pragma unroll
    for (int i = 0; i < 2; i++)
        #pragma unroll
        for (int j = 0; j < 4; j++) wmma::fill_fragment(acc[i][j], 0.f);
    const __half* Abase = A + (long)m0 * lda;
    const __half* Bbase = B + (long)n0 * ldb;
    GEMM_MAINLOOP

    __syncthreads();                        // pipeline dead; stage fp32 tile
    float* Ct = (float*)smh;
    #pragma unroll
    for (int i = 0; i < 2; i++)
        #pragma unroll
        for (int j = 0; j < 4; j++)
            wmma::store_matrix_sync(Ct + (wm0 + 16 * i) * CSTR + wn0 + 16 * j,
                                    acc[i][j], CSTR, wmma::mem_row_major);
    __syncthreads();

    const int section = n0 >> 10;           // 0=q, 1=k, 2=v
    const int cbase   = n0 & 1023;
    if (section < 2) {
        // rope pairs: 128 rows x (2 heads x 32 j) = 8192 pairs, 32/thread
        for (int t = tid; t < 128 * 64; t += 256) {
            int row = t >> 6;
            int p   = t & 63;
            int hin = p >> 5;
            int j   = p & 31;
            int col = hin * 64 + j;
            float a = Ct[row * CSTR + col];
            float b = Ct[row * CSTR + col + 32];
            int l = m0 + row;
            float ang = (float)l * powf(10000.f, -(float)j / 32.f);
            float sn, cn; sincosf(ang, &sn, &cn);
            float r1 = a * cn - b * sn;
            float r2 = b * cn + a * sn;
            int hd = (cbase >> 6) + hin;
            long dst = ((long)hd * SEQ + l) * HDIM + j;
            if (section == 0) {
                r1 *= 0.125f; r2 *= 0.125f;
                split_hl(r1, qh[dst],      ql[dst]);
                split_hl(r2, qh[dst + 32], ql[dst + 32]);
            } else {
                split_hl(r1, kh[dst],      kl[dst]);
                split_hl(r2, kh[dst + 32], kl[dst + 32]);
            }
        }
    } else {
        for (int t = tid; t < 128 * 128; t += 256) {
            int row = t >> 7, col = t & 127;
            int l  = m0 + row;
            int hd = (cbase >> 6) + (col >> 6);
            int j  = col & 63;
            v16[((long)hd * SEQ + l) * HDIM + j] =
                __float2half_rn(Ct[row * CSTR + col]);
        }
    }
}

// ---------------- FFP GEMM with fused SwiGLU -> fp16 mlp -------------------------
// Computes x1 tile (W rows n0..) and x2 tile (W rows 4096+n0..) simultaneously;
// writes silu(x2)*x1. Fragment layouts are element-aligned, so combine in regs.
#define SW_STAGE (3 * 128 * PADK)                    // halves per stage
#define SW_SMEM  (128 * CSTR * (int)sizeof(float))   // 67584 > 2*SW_STAGE*2

__global__ void __launch_bounds__(256) gemm_swiglu(
    const __half* __restrict__ A, int lda,
    const __half* __restrict__ B, int ldb,
    __half* __restrict__ C, int ldc, int K)
{
    extern __shared__ __half smh[];
    GEMM_PROLOG_BODY
    wmma::fragment<wmma::accumulator, 16, 16, 16, float> acc1[2][4], acc2[2][4];
    #pragma unroll
    for (int i = 0; i < 2; i++)
        #pragma unroll
        for (int j = 0; j < 4; j++) {
            wmma::fill_fragment(acc1[i][j], 0.f);
            wmma::fill_fragment(acc2[i][j], 0.f);
        }
    const __half* Abase  = A + (long)m0 * lda;
    const __half* B1base = B + (long)n0 * ldb;
    const __half* B2base = B + (long)(4096 + n0) * ldb;

    #define SW_LOAD(ST, K0)                                                     \
    do {                                                                        \
        __half* sb = smh + (ST) * SW_STAGE;                                     \
        _Pragma("unroll")                                                       \
        for (int t = 0; t < 6; t++) {                                           \
            int c   = tid + t * 256;                                            \
            int arr = c >> 9;                                                   \
            int rem = c & 511;                                                  \
            int row = rem >> 2;                                                 \
            int col = (rem & 3) * 8;                                            \
            const __half* src =                                                 \
                (arr == 0) ? Abase  + (long)row * lda + (K0) + col :            \
                (arr == 1) ? B1base + (long)row * ldb + (K0) + col :            \
                             B2base + (long)row * ldb + (K0) + col;             \
            cp16h(sb + arr * (128 * PADK) + row * PADK + col, src);             \
        }                                                                       \
        asm volatile("cp.async.commit_group;\n" ::);                            \
    } while (0)

    const int nk = K / GBK;
    SW_LOAD(0, 0);
    for (int ks = 0; ks < nk; ks++) {
        asm volatile("cp.async.wait_group 0;\n" ::);
        __syncthreads();
        if (ks + 1 < nk) SW_LOAD((ks + 1) & 1, (ks + 1) * GBK);
        __half* sb  = smh + (ks & 1) * SW_STAGE;
        __half* sA  = sb;
        __half* sB1 = sb + 128 * PADK;
        __half* sB2 = sb + 2 * 128 * PADK;
        #pragma unroll
        for (int k16 = 0; k16 < GBK; k16 += 16) {
            wmma::fragment<wmma::matrix_a, 16, 16, 16, __half, wmma::row_major> af[2];
            #pragma unroll
            for (int i = 0; i < 2; i++)
                wmma::load_matrix_sync(af[i], sA + (wm0 + 16 * i) * PADK + k16, PADK);
            #pragma unroll
            for (int j = 0; j < 4; j++) {
                wmma::fragment<wmma::matrix_b, 16, 16, 16, __half, wmma::col_major> b1, b2;
                wmma::load_matrix_sync(b1, sB1 + (wn0 + 16 * j) * PADK + k16, PADK);
                wmma::load_matrix_sync(b2, sB2 + (wn0 + 16 * j) * PADK + k16, PADK);
                #pragma unroll
                for (int i = 0; i < 2; i++) {
                    wmma::mma_sync(acc1[i][j], af[i], b1, acc1[i][j]);
                    wmma::mma_sync(acc2[i][j], af[i], b2, acc2[i][j]);
                }
            }
        }
    }

    // combine in registers: mlp = silu(x2) * x1
    #pragma unroll
    for (int i = 0; i < 2; i++)
        #pragma unroll
        for (int j = 0; j < 4; j++)
            #pragma unroll
            for (int t = 0; t < acc1[i][j].num_elements; t++) {
                float x2 = acc2[i][j].x[t];
                float sig = 1.f / (1.f + __expf(-x2));
                acc1[i][j].x[t] *= x2 * sig;
            }

    __syncthreads();
    float* Ct = (float*)smh;
    #pragma unroll
    for (int i = 0; i < 2; i++)
        #pragma unroll
        for (int j = 0; j < 4; j++)
            wmma::store_matrix_sync(Ct + (wm0 + 16 * i) * CSTR + wn0 + 16 * j,
                                    acc1[i][j], CSTR, wmma::mem_row_major);
    __syncthreads();
    #pragma unroll
    for (int t = 0; t < 16; t++) {
        int c = (tid + t * 256) * 4;
        int row = c >> 7, col = c & 127;
        float4 v = *(float4*)(Ct + row * CSTR + col);
        __align__(8) __half hh[4] = {__float2half_rn(v.x), __float2half_rn(v.y),
                                     __float2half_rn(v.z), __float2half_rn(v.w)};
        *(uint2*)(C + (long)(m0 + row) * ldc + n0 + col) = *(uint2*)hh;
    }
}

// ---------------- Flash attention Q128: 3-pass S, 1-pass fp16 PV ----------------
#define QSTR 80
#define FSTR 68
#define STG  (64 * QSTR)
#define AT4_SMEM (6 * STG * 2 + 2 * 128 * FSTR * 4)   // 131072 B

__global__ void __launch_bounds__(512, 1) attn4(
    const bf16* __restrict__ Qh, const bf16* __restrict__ Ql,
    const bf16* __restrict__ Kh, const bf16* __restrict__ Kl,
    const __half* __restrict__ V16,
    __half* __restrict__ out)
{
    extern __shared__ char smraw[];
    bf16*   sK = (bf16*)smraw;
    __half* sV = (__half*)(smraw + 4 * STG * 2);
    float*  Sf = (float*)(smraw + 6 * STG * 2);
    float*  Of = Sf + 128 * FSTR;

    const int h     = blockIdx.x;
    const int qb    = (int)gridDim.y - 1 - (int)blockIdx.y;
    const int tid   = threadIdx.x;
    const int warp  = tid >> 5;
    const int qbase = qb * 128;
    const int rt    = warp >> 1;
    const int chalf = (warp & 1) * 32;

    bf16* sQh = sK;
    bf16* sQl = sK + 128 * QSTR;
    const long qoff = ((long)h * SEQ + qbase) * HDIM;
    #pragma unroll
    for (int t = 0; t < 2; t++) {
        int c = tid + t * 512;
        int row = c >> 3, ch = (c & 7) * 8;
        cp16b(sQh + row * QSTR + ch, Qh + qoff + row * HDIM + ch);
        cp16b(sQl + row * QSTR + ch, Ql + qoff + row * HDIM + ch);
    }
    asm volatile("cp.async.commit_group;\n" ::);
    asm volatile("cp.async.wait_group 0;\n" ::);
    __syncthreads();

    wmma::fragment<wmma::matrix_a, 16, 16, 16, bf16, wmma::row_major> qhf[4], qlf[4];
    #pragma unroll
    for (int ks = 0; ks < 4; ks++) {
        wmma::load_matrix_sync(qhf[ks], sQh + rt * 16 * QSTR + ks * 16, QSTR);
        wmma::load_matrix_sync(qlf[ks], sQl + rt * 16 * QSTR + ks * 16, QSTR);
    }
    for (int i = tid; i < 128 * FSTR; i += 512) Of[i] = 0.f;
    __syncthreads();

    #define AT_LOAD(ST, KB)                                                     \
    do {                                                                        \
        const long koff = ((long)h * SEQ + (KB) * 64) * HDIM;                   \
        bf16*   dKh = sK + (ST) * 2 * STG;                                      \
        bf16*   dKl = dKh + STG;                                                \
        __half* dV  = sV + (ST) * STG;                                          \
        int c = tid;                                                            \
        int row = c >> 3, ch = (c & 7) * 8;                                     \
        cp16b(dKh + row * QSTR + ch, Kh  + koff + row * HDIM + ch);             \
        cp16b(dKl + row * QSTR + ch, Kl  + koff + row * HDIM + ch);             \
        cp16h(dV  + row * QSTR + ch, V16 + koff + row * HDIM + ch);             \
        asm volatile("cp.async.commit_group;\n" ::);                            \
    } while (0)

    const int r  = tid >> 2;
    const int cs = (tid & 3) * 16;
    float mrow = -1e30f, lsum = 0.f, alpha = 0.f;

    const int nkb = (qbase + 128) >> 6;
    AT_LOAD(0, 0);

    for (int kb = 0; kb < nkb; kb++) {
        const int st = kb & 1;
        asm volatile("cp.async.wait_group 0;\n" ::);
        __syncthreads();
        if (kb + 1 < nkb) AT_LOAD(st ^ 1, kb + 1);

        bf16*   cKh = sK + st * 2 * STG;
        bf16*   cKl = cKh + STG;
        __half* cV  = sV + st * STG;
        __half* P   = (__half*)cKh;

        #pragma unroll
        for (int ct = 0; ct < 2; ct++) {
            const int col0 = chalf + ct * 16;
            wmma::fragment<wmma::accumulator, 16, 16, 16, float> acc;
            wmma::fill_fragment(acc, 0.f);
            #pragma unroll
            for (int ks = 0; ks < 4; ks++) {
                wmma::fragment<wmma::matrix_b, 16, 16, 16, bf16, wmma::col_major> bh, bl;
                wmma::load_matrix_sync(bh, cKh + col0 * QSTR + ks * 16, QSTR);
                wmma::load_matrix_sync(bl, cKl + col0 * QSTR + ks * 16, QSTR);
                wmma::mma_sync(acc, qhf[ks], bl, acc);
                wmma::mma_sync(acc, qlf[ks], bh, acc);
                wmma::mma_sync(acc, qhf[ks], bh, acc);
            }
            wmma::store_matrix_sync(Sf + rt * 16 * FSTR + col0, acc, FSTR,
                                    wmma::mem_row_major);
        }
        __syncthreads();

        const int kbase = kb * 64;
        float s[16];
        #pragma unroll
        for (int j = 0; j < 16; j++) s[j] = Sf[r * FSTR + cs + j];
        if (kbase + 64 > qbase) {
            #pragma unroll
            for (int j = 0; j < 16; j++)
                if (kbase + cs + j > qbase + r) s[j] = -1e30f;
        }
        float mloc = s[0];
        #pragma unroll
        for (int j = 1; j < 16; j++) mloc = fmaxf(mloc, s[j]);
        mloc = fmaxf(mloc, __shfl_xor_sync(0xffffffffu, mloc, 1));
        mloc = fmaxf(mloc, __shfl_xor_sync(0xffffffffu, mloc, 2));
        const float mnew = fmaxf(mrow, mloc);
        alpha = __expf(mrow - mnew);

        float ps = 0.f;
        #pragma unroll
        for (int j = 0; j < 16; j++) {
            float p = __expf(s[j] - mnew);
            ps += p;
            P[r * QSTR + cs + j] = __float2half_rn(p);
        }
        ps += __shfl_xor_sync(0xffffffffu, ps, 1);
        ps += __shfl_xor_sync(0xffffffffu, ps, 2);
        lsum = lsum * alpha + ps;
        mrow = mnew;
        __syncthreads();

        #pragma unroll
        for (int ct = 0; ct < 2; ct++) {
            const int col0 = chalf + ct * 16;
            wmma::fragment<wmma::accumulator, 16, 16, 16, float> acc;
            wmma::fill_fragment(acc, 0.f);
            #pragma unroll
            for (int js = 0; js < 4; js++) {
                wmma::fragment<wmma::matrix_a, 16, 16, 16, __half, wmma::row_major> pf;
                wmma::load_matrix_sync(pf, P + rt * 16 * QSTR + js * 16, QSTR);
                wmma::fragment<wmma::matrix_b, 16, 16, 16, __half, wmma::row_major> vf;
                wmma::load_matrix_sync(vf, cV + js * 16 * QSTR + col0, QSTR);
                wmma::mma_sync(acc, pf, vf, acc);
            }
            wmma::store_matrix_sync(Sf + rt * 16 * FSTR + col0, acc, FSTR,
                                    wmma::mem_row_major);
        }
        __syncthreads();

        #pragma unroll
        for (int j = 0; j < 16; j++) {
            int o = r * FSTR + cs + j;
            Of[o] = Of[o] * alpha + Sf[o];
        }
    }

    __syncthreads();
    const float invl = 1.f / lsum;
    __half* orow = out + (long)(qbase + r) * DMOD + h * HDIM + cs;
    #pragma unroll
    for (int j = 0; j < 16; j++)
        orow[j] = __float2half_rn(Of[r * FSTR + cs + j] * invl);
}

// ---------------- launch -----------------------------------------------------------
extern "C" void kernel_launch(void* const* d_in, const int* in_sizes, int n_in,
                              void* d_out, int out_size) {
    const float* x      = (const float*)d_in[0];
    const float* W_attn = (const float*)d_in[2];
    const float* W_out  = (const float*)d_in[3];
    const float* W_ffp  = (const float*)d_in[4];
    const float* W_ffo  = (const float*)d_in[5];
    float* out = (float*)d_out;

    float *h;
    __half *xn16, *at16, *hn16, *mlp16, *Wa16, *Wo16, *Wp16, *Wf16, *v16;
    bf16 *qh, *ql, *kh, *kl;
    cudaGetSymbolAddress((void**)&h,    g_h);
    cudaGetSymbolAddress((void**)&xn16, g_xn16);
    cudaGetSymbolAddress((void**)&at16, g_at16);
    cudaGetSymbolAddress((void**)&hn16, g_hn16);
    cudaGetSymbolAddress((void**)&mlp16,g_mlp16);
    cudaGetSymbolAddress((void**)&Wa16, g_Wa16);
    cudaGetSymbolAddress((void**)&Wo16, g_Wo16);
    cudaGetSymbolAddress((void**)&Wp16, g_Wp16);
    cudaGetSymbolAddress((void**)&Wf16, g_Wf16);
    cudaGetSymbolAddress((void**)&qh, g_qh); cudaGetSymbolAddress((void**)&ql, g_ql);
    cudaGetSymbolAddress((void**)&kh, g_kh); cudaGetSymbolAddress((void**)&kl, g_kl);
    cudaGetSymbolAddress((void**)&v16, g_v16);

    cudaFuncSetAttribute(attn4,
                         cudaFuncAttributeMaxDynamicSharedMemorySize, AT4_SMEM);
    cudaFuncSetAttribute(gemm_h,
                         cudaFuncAttributeMaxDynamicSharedMemorySize, GH_SMEM);
    cudaFuncSetAttribute(gemm_qkv_rope,
                         cudaFuncAttributeMaxDynamicSharedMemorySize, GEP_SMEM);
    cudaFuncSetAttribute(gemm_swiglu,
                         cudaFuncAttributeMaxDynamicSharedMemorySize, SW_SMEM);

    // fused weight converts
    {
        int n0 = 3 * DMOD * DMOD, n1 = DMOD * DMOD,
            n2 = DMLP * DMOD,     n3 = DMOD * DMLP / 2;
        long total = (long)n0 + n1 + n2 + n3;
        cvt_all<<<(int)(total / 8 / 256), 256>>>(W_attn, Wa16, n0, W_out, Wo16, n1,
                                                 W_ffp, Wp16, n2, W_ffo, Wf16, n3);
    }

    // 1) xn = LN(x) -> fp16
    ln_kernel<<<SEQ, 256>>>(x, xn16);

    // 2) qkv GEMM + RoPE + head-major split (fused)
    gemm_qkv_rope<<<dim3(3 * DMOD / 128, SEQ / 128), 256, GEP_SMEM>>>(
        xn16, DMOD, Wa16, DMOD, DMOD, qh, ql, kh, kl, v16);

    // 3) attention (Q128) -> fp16
    attn4<<<dim3(NHEAD, SEQ / 128), 512, AT4_SMEM>>>(qh, ql, kh, kl, v16, at16);

    // 4) h = attn @ W_out^T + x  (fp32 out)
    gemm_h<<<dim3(DMOD / 128, SEQ / 128), 256, GH_SMEM>>>(
        at16, DMOD, Wo16, DMOD, h, DMOD, x, DMOD);

    // 5) hn = LN(h) -> fp16
    ln_kernel<<<SEQ, 256>>>(h, hn16);

    // 6) mlp = silu(x2)*x1 fused into the FFP GEMM -> fp16
    gemm_swiglu<<<dim3((DMLP / 2) / 128, SEQ / 128), 256, SW_SMEM>>>(
        hn16, DMOD, Wp16, DMOD, mlp16, DMLP / 2, DMOD);

    // 7) out = mlp @ W_ffo^T + h  (fp32 out)
    gemm_h<<<dim3(DMOD / 128, SEQ / 128), 256, GH_SMEM>>>(
        mlp16, DMLP / 2, Wf16, DMLP / 2, out, DMOD, h, DMLP / 2);
}

// round 16
// speedup vs baseline: 1.0559x; 1.0559x over previous
#include <cuda_runtime.h>
#include <cuda_bf16.h>
#include <cuda_fp16.h>
#include <mma.h>
#include <math.h>
#include <cstdint>

using namespace nvcuda;
typedef __nv_bfloat16 bf16;

#define SEQ   2048
#define DMOD  1024
#define NHEAD 16
#define HDIM  64
#define DMLP  8192

// ---------------- scratch -----------------------------------------------------
__device__ float  g_qkv [SEQ * 3 * DMOD];
__device__ float  g_h   [SEQ * DMOD];
__device__ __half g_xn16 [SEQ * DMOD];
__device__ __half g_at16 [SEQ * DMOD];
__device__ __half g_hn16 [SEQ * DMOD];
__device__ __half g_g16 [SEQ * DMLP];
__device__ __half g_mlp16[SEQ * (DMLP / 2)];
__device__ __half g_Wa16[3 * DMOD * DMOD];
__device__ __half g_Wo16[DMOD * DMOD];
__device__ __half g_Wp16[DMLP * DMOD];
__device__ __half g_Wf16[DMOD * DMLP / 2];
// head-major RoPE'd q/k (bf16 hi/lo) and v (fp16):  [h][l][64]
__device__ bf16   g_qh[SEQ * DMOD], g_ql[SEQ * DMOD];
__device__ bf16   g_kh[SEQ * DMOD], g_kl[SEQ * DMOD];
__device__ __half g_v16[SEQ * DMOD];

__device__ __forceinline__ void split_hl(float v, bf16& h, bf16& l) {
    h = __float2bfloat16(v);
    l = __float2bfloat16(v - __bfloat162float(h));
}
__device__ __forceinline__ void cp16b(bf16* dst, const bf16* src) {
    uint32_t s = (uint32_t)__cvta_generic_to_shared(dst);
    asm volatile("cp.async.cg.shared.global [%0], [%1], 16;\n" :: "r"(s), "l"(src));
}
__device__ __forceinline__ void cp16h(__half* dst, const __half* src) {
    uint32_t s = (uint32_t)__cvta_generic_to_shared(dst);
    asm volatile("cp.async.cg.shared.global [%0], [%1], 16;\n" :: "r"(s), "l"(src));
}

// ---------------- fused fp32 -> fp16 convert for all 4 weights -----------------
__global__ void __launch_bounds__(256) cvt_all(
    const float* __restrict__ s0, __half* __restrict__ d0, int n0,
    const float* __restrict__ s1, __half* __restrict__ d1, int n1,
    const float* __restrict__ s2, __half* __restrict__ d2, int n2,
    const float* __restrict__ s3, __half* __restrict__ d3, int n3)
{
    long i = ((long)blockIdx.x * 256 + threadIdx.x) * 8;
    const float* s; __half* d; long off = i;
    if (off < n0)              { s = s0; d = d0; }
    else if ((off -= n0) < n1) { s = s1; d = d1; }
    else if ((off -= n1) < n2) { s = s2; d = d2; }
    else if ((off -= n2) < n3) { s = s3; d = d3; }
    else return;
    float4 v0 = *(const float4*)(s + off);
    float4 v1 = *(const float4*)(s + off + 4);
    float a[8] = {v0.x, v0.y, v0.z, v0.w, v1.x, v1.y, v1.z, v1.w};
    __align__(16) __half hh[8];
    #pragma unroll
    for (int e = 0; e < 8; e++) hh[e] = __float2half_rn(a[e]);
    *(uint4*)(d + off) = *(uint4*)hh;
}

// ---------------- LayerNorm -> fp16 ---------------------------------------------
__global__ void __launch_bounds__(256) ln_kernel(const float* __restrict__ x,
                                                 __half* __restrict__ y) {
    __shared__ float row[DMOD];
    __shared__ float red[256];
    const int r   = blockIdx.x;
    const int tid = threadIdx.x;
    const float* xr = x + (long)r * DMOD;

    float s = 0.f;
    #pragma unroll
    for (int i = 0; i < 4; i++) {
        float v = xr[tid + i * 256];
        row[tid + i * 256] = v;
        s += v;
    }
    red[tid] = s; __syncthreads();
    #pragma unroll
    for (int off = 128; off > 0; off >>= 1) {
        if (tid < off) red[tid] += red[tid + off];
        __syncthreads();
    }
    const float mu = red[0] * (1.f / DMOD);
    __syncthreads();

    float ss = 0.f;
    #pragma unroll
    for (int i = 0; i < 4; i++) {
        float d = row[tid + i * 256] - mu;
        ss += d * d;
    }
    red[tid] = ss; __syncthreads();
    #pragma unroll
    for (int off = 128; off > 0; off >>= 1) {
        if (tid < off) red[tid] += red[tid + off];
        __syncthreads();
    }
    const float inv = rsqrtf(red[0] * (1.f / DMOD) + 1e-5f);

    __half* yr = y + (long)r * DMOD;
    #pragma unroll
    for (int i = 0; i < 4; i++) {
        int c = tid + i * 256;
        yr[c] = __float2half_rn((row[c] - mu) * inv);
    }
}

// ---------------- common GEMM pieces --------------------------------------------
#define GBK   32
#define PADK  40
#define CSTR  132
#define GH_SMEM   (2 * 2 * 128 * PADK * (int)sizeof(__half))   // 40960 B
#define GH16_SMEM (128 * CSTR * (int)sizeof(float))            // 67584 B

#define GEMM_PROLOG_BODY                                                        \
    const int tid  = threadIdx.x;                                               \
    const int m0   = blockIdx.y * 128;                                          \
    const int n0   = blockIdx.x * 128;                                          \
    const int warp = tid >> 5;                                                  \
    const int wm0  = (warp & 3) * 32;                                           \
    const int wn0  = (warp >> 2) * 64;

#define GH_LOAD(ST, K0)                                                        \
do {                                                                           \
    __half* sb = smh + (ST) * (2 * 128 * PADK);                                \
    _Pragma("unroll")                                                          \
    for (int t = 0; t < 4; t++) {                                              \
        int c   = tid + t * 256;                                               \
        int arr = c >> 9;                                                      \
        int rem = c & 511;                                                     \
        int row = rem >> 2;                                                    \
        int col = (rem & 3) * 8;                                               \
        const __half* src = arr ? Bbase + (long)row * ldb + (K0) + col         \
                                : Abase + (long)row * lda + (K0) + col;        \
        cp16h(sb + arr * (128 * PADK) + row * PADK + col, src);                \
    }                                                                          \
    asm volatile("cp.async.commit_group;\n" ::);                               \
} while (0)

#define GEMM_MAINLOOP                                                           \
    const int nk = K / GBK;                                                     \
    GH_LOAD(0, 0);                                                              \
    for (int ks = 0; ks < nk; ks++) {                                           \
        asm volatile("cp.async.wait_group 0;\n" ::);                            \
        __syncthreads();                                                        \
        if (ks + 1 < nk) GH_LOAD((ks + 1) & 1, (ks + 1) * GBK);                 \
        __half* sb = smh + (ks & 1) * (2 * 128 * PADK);                         \
        __half* sA = sb;                                                        \
        __half* sB = sb + 128 * PADK;                                           \
        _Pragma("unroll")                                                       \
        for (int k16 = 0; k16 < GBK; k16 += 16) {                               \
            wmma::fragment<wmma::matrix_a, 16, 16, 16, __half,                  \
                           wmma::row_major> af[2];                              \
            _Pragma("unroll")                                                   \
            for (int i = 0; i < 2; i++)                                         \
                wmma::load_matrix_sync(af[i],                                   \
                    sA + (wm0 + 16 * i) * PADK + k16, PADK);                    \
            _Pragma("unroll")                                                   \
            for (int j = 0; j < 4; j++) {                                       \
                wmma::fragment<wmma::matrix_b, 16, 16, 16, __half,              \
                               wmma::col_major> bfr;                            \
                wmma::load_matrix_sync(bfr,                                     \
                    sB + (wn0 + 16 * j) * PADK + k16, PADK);                    \
                _Pragma("unroll")                                               \
                for (int i = 0; i < 2; i++)                                     \
                    wmma::mma_sync(acc[i][j], af[i], bfr, acc[i][j]);           \
            }                                                                   \
        }                                                                       \
    }

// ---------------- GEMM -> fp32 C (+Res) ------------------------------------------
__global__ void __launch_bounds__(256, 2) gemm_h(
    const __half* __restrict__ A, int lda,
    const __half* __restrict__ B, int ldb,
    float* __restrict__ C, int ldc, const float* __restrict__ Res, int K)
{
    extern __shared__ __half smh[];
    GEMM_PROLOG_BODY
    wmma::fragment<wmma::accumulator, 16, 16, 16, float> acc[2][4];
    #pragma unroll
    for (int i = 0; i < 2; i++)
        #pragma unroll
        for (int j = 0; j < 4; j++) {
            if (Res) {
                const float* rp = Res + (long)(m0 + wm0 + 16 * i) * ldc
                                      + n0 + wn0 + 16 * j;
                wmma::load_matrix_sync(acc[i][j], rp, ldc, wmma::mem_row_major);
            } else {
                wmma::fill_fragment(acc[i][j], 0.f);
            }
        }
    const __half* Abase = A + (long)m0 * lda;
    const __half* Bbase = B + (long)n0 * ldb;
    GEMM_MAINLOOP
    #pragma unroll
    for (int i = 0; i < 2; i++)
        #pragma unroll
        for (int j = 0; j < 4; j++) {
            float* cp = C + (long)(m0 + wm0 + 16 * i) * ldc + n0 + wn0 + 16 * j;
            wmma::store_matrix_sync(cp, acc[i][j], ldc, wmma::mem_row_major);
        }
}

// ---------------- GEMM -> fp16 C (smem-staged epilogue) --------------------------
__global__ void __launch_bounds__(256, 2) gemm_h16(
    const __half* __restrict__ A, int lda,
    const __half* __restrict__ B, int ldb,
    __half* __restrict__ C, int ldc, int K)
{
    extern __shared__ __half smh[];
    GEMM_PROLOG_BODY
    wmma::fragment<wmma::accumulator, 16, 16, 16, float> acc[2][4];
    #pragma unroll
    for (int i = 0; i < 2; i++)
        #pragma unroll
        for (int j = 0; j < 4; j++) wmma::fill_fragment(acc[i][j], 0.f);
    const __half* Abase = A + (long)m0 * lda;
    const __half* Bbase = B + (long)n0 * ldb;
    GEMM_MAINLOOP

    __syncthreads();
    float* Ct = (float*)smh;
    #pragma unroll
    for (int i = 0; i < 2; i++)
        #pragma unroll
        for (int j = 0; j < 4; j++)
            wmma::store_matrix_sync(Ct + (wm0 + 16 * i) * CSTR + wn0 + 16 * j,
                                    acc[i][j], CSTR, wmma::mem_row_major);
    __syncthreads();
    #pragma unroll
    for (int t = 0; t < 16; t++) {
        int c = (tid + t * 256) * 4;
        int row = c >> 7, col = c & 127;
        float4 v = *(float4*)(Ct + row * CSTR + col);
        __align__(8) __half hh[4] = {__float2half_rn(v.x), __float2half_rn(v.y),
                                     __float2half_rn(v.z), __float2half_rn(v.w)};
        *(uint2*)(C + (long)(m0 + row) * ldc + n0 + col) = *(uint2*)hh;
    }
}

// ---------------- RoPE + head-major split: q,k bf16 hi/lo; v fp16 ---------------
__global__ void __launch_bounds__(256) rope_split(
    const float* __restrict__ qkv,
    bf16* __restrict__ qh, bf16* __restrict__ ql,
    bf16* __restrict__ kh, bf16* __restrict__ kl,
    __half* __restrict__ v16)
{
    const int idx = blockIdx.x * 256 + threadIdx.x;
    if (idx >= SEQ * NHEAD * 32) return;
    const int j = idx & 31;
    const int h = (idx >> 5) & (NHEAD - 1);
    const int l = idx >> 9;

    const float inv_freq = powf(10000.f, -(float)j / 32.f);
    const float ang = (float)l * inv_freq;
    float c, s;
    sincosf(ang, &s, &c);

    const float* qp = qkv + (long)l * (3 * DMOD) + h * HDIM + j;
    const float q1 = qp[0], q2 = qp[32];
    const float k1 = qp[DMOD], k2 = qp[DMOD + 32];
    const float v1 = qp[2 * DMOD], v2 = qp[2 * DMOD + 32];

    const long dst = ((long)h * SEQ + l) * HDIM + j;
    split_hl((q1 * c - q2 * s) * 0.125f, qh[dst],      ql[dst]);
    split_hl((q2 * c + q1 * s) * 0.125f, qh[dst + 32], ql[dst + 32]);
    split_hl(k1 * c - k2 * s,            kh[dst],      kl[dst]);
    split_hl(k2 * c + k1 * s,            kh[dst + 32], kl[dst + 32]);
    v16[dst]      = __float2half_rn(v1);
    v16[dst + 32] = __float2half_rn(v2);
}

// ---------------- Flash attention Q128, pipelined: QK(kb+1) || PV(kb) -----------
#define QSTR 80
#define FSTR 68
#define STG  (64 * QSTR)
// smem: sK 40960 | sV 20480 | Sf x2 69632 | Of 34816  = 165888
#define AT5_SMEM (4 * STG * 2 + 2 * STG * 2 + 2 * 128 * FSTR * 4 + 128 * FSTR * 4)

__global__ void __launch_bounds__(512, 1) attn5(
    const bf16* __restrict__ Qh, const bf16* __restrict__ Ql,
    const bf16* __restrict__ Kh, const bf16* __restrict__ Kl,
    const __half* __restrict__ V16,
    __half* __restrict__ out)
{
    extern __shared__ char smraw[];
    bf16*   sK  = (bf16*)smraw;                          // 2 stages x (Kh,Kl)
    __half* sV  = (__half*)(smraw + 4 * STG * 2);        // 2 stages
    float*  SfB = (float*)(smraw + 6 * STG * 2);         // 2 x (128*FSTR)
    float*  Of  = SfB + 2 * 128 * FSTR;

    const int h     = blockIdx.x;
    const int qb    = (int)gridDim.y - 1 - (int)blockIdx.y;
    const int tid   = threadIdx.x;
    const int warp  = tid >> 5;
    const int qbase = qb * 128;
    const int rt    = warp >> 1;
    const int chalf = (warp & 1) * 32;

    // ---- stage Q (128 rows hi/lo) through the full sK area
    bf16* sQh = sK;
    bf16* sQl = sK + 128 * QSTR;
    const long qoff = ((long)h * SEQ + qbase) * HDIM;
    #pragma unroll
    for (int t = 0; t < 2; t++) {
        int c = tid + t * 512;
        int row = c >> 3, ch = (c & 7) * 8;
        cp16b(sQh + row * QSTR + ch, Qh + qoff + row * HDIM + ch);
        cp16b(sQl + row * QSTR + ch, Ql + qoff + row * HDIM + ch);
    }
    asm volatile("cp.async.commit_group;\n" ::);
    asm volatile("cp.async.wait_group 0;\n" ::);
    __syncthreads();

    wmma::fragment<wmma::matrix_a, 16, 16, 16, bf16, wmma::row_major> qhf[4], qlf[4];
    #pragma unroll
    for (int ks = 0; ks < 4; ks++) {
        wmma::load_matrix_sync(qhf[ks], sQh + rt * 16 * QSTR + ks * 16, QSTR);
        wmma::load_matrix_sync(qlf[ks], sQl + rt * 16 * QSTR + ks * 16, QSTR);
    }
    for (int i = tid; i < 128 * FSTR; i += 512) Of[i] = 0.f;
    __syncthreads();                                    // Q read; sK reusable

    #define AT_LOAD(ST, KB)                                                     \
    do {                                                                        \
        const long koff = ((long)h * SEQ + (KB) * 64) * HDIM;                   \
        bf16*   dKh = sK + (ST) * 2 * STG;                                      \
        bf16*   dKl = dKh + STG;                                                \
        __half* dV  = sV + (ST) * STG;                                          \
        int row = tid >> 3, ch = (tid & 7) * 8;                                 \
        cp16b(dKh + row * QSTR + ch, Kh  + koff + row * HDIM + ch);             \
        cp16b(dKl + row * QSTR + ch, Kl  + koff + row * HDIM + ch);             \
        cp16h(dV  + row * QSTR + ch, V16 + koff + row * HDIM + ch);             \
        asm volatile("cp.async.commit_group;\n" ::);                            \
    } while (0)

    #define QK_MMA(KST, SFDST)                                                  \
    do {                                                                        \
        bf16* xKh = sK + (KST) * 2 * STG;                                       \
        bf16* xKl = xKh + STG;                                                  \
        _Pragma("unroll")                                                       \
        for (int ct = 0; ct < 2; ct++) {                                        \
            const int col0 = chalf + ct * 16;                                   \
            wmma::fragment<wmma::accumulator, 16, 16, 16, float> acc;           \
            wmma::fill_fragment(acc, 0.f);                                      \
            _Pragma("unroll")                                                   \
            for (int ks = 0; ks < 4; ks++) {                                    \
                wmma::fragment<wmma::matrix_b, 16, 16, 16, bf16,                \
                               wmma::col_major> bh, bl;                         \
                wmma::load_matrix_sync(bh, xKh + col0 * QSTR + ks * 16, QSTR);  \
                wmma::load_matrix_sync(bl, xKl + col0 * QSTR + ks * 16, QSTR);  \
                wmma::mma_sync(acc, qhf[ks], bl, acc);                          \
                wmma::mma_sync(acc, qlf[ks], bh, acc);                          \
                wmma::mma_sync(acc, qhf[ks], bh, acc);                          \
            }                                                                   \
            wmma::store_matrix_sync((SFDST) + rt * 16 * FSTR + col0, acc, FSTR, \
                                    wmma::mem_row_major);                       \
        }                                                                       \
    } while (0)

    const int r  = tid >> 2;
    const int cs = (tid & 3) * 16;
    float mrow = -1e30f, lsum = 0.f, alpha = 0.f;

    const int nkb = (qbase + 128) >> 6;
    AT_LOAD(0, 0);
    if (nkb > 1) AT_LOAD(1, 1);
    asm volatile("cp.async.wait_group 0;\n" ::);
    __syncthreads();

    QK_MMA(0, SfB);                                     // S(0) -> Sf[0]
    __syncthreads();

    for (int kb = 0; kb < nkb; kb++) {
        const int st = kb & 1;
        float*  Sc = SfB + st * (128 * FSTR);           // S(kb), then T(kb)
        float*  Sn = SfB + (st ^ 1) * (128 * FSTR);
        __half* P  = (__half*)(sK + st * 2 * STG);      // over stage-st Kh/Kl
        __half* cV = sV + st * STG;

        // ---- softmax on S(kb); write P (fp16)
        const int kbase = kb * 64;
        float s[16];
        #pragma unroll
        for (int j = 0; j < 16; j++) s[j] = Sc[r * FSTR + cs + j];
        if (kbase + 64 > qbase) {
            #pragma unroll
            for (int j = 0; j < 16; j++)
                if (kbase + cs + j > qbase + r) s[j] = -1e30f;
        }
        float mloc = s[0];
        #pragma unroll
        for (int j = 1; j < 16; j++) mloc = fmaxf(mloc, s[j]);
        mloc = fmaxf(mloc, __shfl_xor_sync(0xffffffffu, mloc, 1));
        mloc = fmaxf(mloc, __shfl_xor_sync(0xffffffffu, mloc, 2));
        const float mnew = fmaxf(mrow, mloc);
        alpha = __expf(mrow - mnew);

        float ps = 0.f;
        #pragma unroll
        for (int j = 0; j < 16; j++) {
            float p = __expf(s[j] - mnew);
            ps += p;
            P[r * QSTR + cs + j] = __float2half_rn(p);
        }
        ps += __shfl_xor_sync(0xffffffffu, ps, 1);
        ps += __shfl_xor_sync(0xffffffffu, ps, 2);
        lsum = lsum * alpha + ps;
        mrow = mnew;

        asm volatile("cp.async.wait_group 0;\n" ::);    // K(kb+1)/V ready
        __syncthreads();

        // ---- fused mma region: PV(kb) -> Sc  AND  QK(kb+1) -> Sn
        #pragma unroll
        for (int ct = 0; ct < 2; ct++) {
            const int col0 = chalf + ct * 16;
            wmma::fragment<wmma::accumulator, 16, 16, 16, float> acc;
            wmma::fill_fragment(acc, 0.f);
            #pragma unroll
            for (int js = 0; js < 4; js++) {
                wmma::fragment<wmma::matrix_a, 16, 16, 16, __half, wmma::row_major> pf;
                wmma::load_matrix_sync(pf, P + rt * 16 * QSTR + js * 16, QSTR);
                wmma::fragment<wmma::matrix_b, 16, 16, 16, __half, wmma::row_major> vf;
                wmma::load_matrix_sync(vf, cV + js * 16 * QSTR + col0, QSTR);
                wmma::mma_sync(acc, pf, vf, acc);
            }
            wmma::store_matrix_sync(Sc + rt * 16 * FSTR + col0, acc, FSTR,
                                    wmma::mem_row_major);
        }
        if (kb + 1 < nkb) QK_MMA(st ^ 1, Sn);
        __syncthreads();

        // ---- O = alpha*O + T ; prefetch K/V(kb+2) into stage st
        #pragma unroll
        for (int j = 0; j < 16; j++) {
            int o = r * FSTR + cs + j;
            Of[o] = Of[o] * alpha + Sc[o];
        }
        if (kb + 2 < nkb) AT_LOAD(st, kb + 2);
    }

    __syncthreads();
    const float invl = 1.f / lsum;
    __half* orow = out + (long)(qbase + r) * DMOD + h * HDIM + cs;
    #pragma unroll
    for (int j = 0; j < 16; j++)
        orow[j] = __float2half_rn(Of[r * FSTR + cs + j] * invl);
}

// ---------------- SwiGLU (fp16 in) -> fp16 ----------------------------------------
__global__ void __launch_bounds__(256) swiglu_kernel(const __half* __restrict__ g,
                                                     __half* __restrict__ o) {
    const int idx = blockIdx.x * 256 + threadIdx.x;
    if (idx >= SEQ * (DMLP / 2)) return;
    const int rw = idx >> 12;
    const int c  = idx & 4095;
    const float x1 = __half2float(g[(long)rw * DMLP + c]);
    const float x2 = __half2float(g[(long)rw * DMLP + (DMLP / 2) + c]);
    const float sig = 1.f / (1.f + __expf(-x2));
    o[idx] = __float2half_rn(x2 * sig * x1);
}

// ---------------- launch -----------------------------------------------------------
extern "C" void kernel_launch(void* const* d_in, const int* in_sizes, int n_in,
                              void* d_out, int out_size) {
    const float* x      = (const float*)d_in[0];
    const float* W_attn = (const float*)d_in[2];
    const float* W_out  = (const float*)d_in[3];
    const float* W_ffp  = (const float*)d_in[4];
    const float* W_ffo  = (const float*)d_in[5];
    float* out = (float*)d_out;

    float *qkv, *h;
    __half *xn16, *at16, *hn16, *g16, *mlp16, *Wa16, *Wo16, *Wp16, *Wf16, *v16;
    bf16 *qh, *ql, *kh, *kl;
    cudaGetSymbolAddress((void**)&qkv,  g_qkv);
    cudaGetSymbolAddress((void**)&h,    g_h);
    cudaGetSymbolAddress((void**)&xn16, g_xn16);
    cudaGetSymbolAddress((void**)&at16, g_at16);
    cudaGetSymbolAddress((void**)&hn16, g_hn16);
    cudaGetSymbolAddress((void**)&g16,  g_g16);
    cudaGetSymbolAddress((void**)&mlp16,g_mlp16);
    cudaGetSymbolAddress((void**)&Wa16, g_Wa16);
    cudaGetSymbolAddress((void**)&Wo16, g_Wo16);
    cudaGetSymbolAddress((void**)&Wp16, g_Wp16);
    cudaGetSymbolAddress((void**)&Wf16, g_Wf16);
    cudaGetSymbolAddress((void**)&qh, g_qh); cudaGetSymbolAddress((void**)&ql, g_ql);
    cudaGetSymbolAddress((void**)&kh, g_kh); cudaGetSymbolAddress((void**)&kl, g_kl);
    cudaGetSymbolAddress((void**)&v16, g_v16);

    cudaFuncSetAttribute(attn5,
                         cudaFuncAttributeMaxDynamicSharedMemorySize, AT5_SMEM);
    cudaFuncSetAttribute(gemm_h,
                         cudaFuncAttributeMaxDynamicSharedMemorySize, GH_SMEM);
    cudaFuncSetAttribute(gemm_h16,
                         cudaFuncAttributeMaxDynamicSharedMemorySize, GH16_SMEM);

    // fused weight converts
    {
        int n0 = 3 * DMOD * DMOD, n1 = DMOD * DMOD,
            n2 = DMLP * DMOD,     n3 = DMOD * DMLP / 2;
        long total = (long)n0 + n1 + n2 + n3;
        cvt_all<<<(int)(total / 8 / 256), 256>>>(W_attn, Wa16, n0, W_out, Wo16, n1,
                                                 W_ffp, Wp16, n2, W_ffo, Wf16, n3);
    }

    // 1) xn = LN(x) -> fp16
    ln_kernel<<<SEQ, 256>>>(x, xn16);

    // 2) qkv = xn @ W_attn^T  (fp32 out)
    gemm_h<<<dim3(3 * DMOD / 128, SEQ / 128), 256, GH_SMEM>>>(
        xn16, DMOD, Wa16, DMOD, qkv, 3 * DMOD, nullptr, DMOD);

    // 3) RoPE + head-major split
    rope_split<<<(SEQ * NHEAD * 32 + 255) / 256, 256>>>(qkv, qh, ql, kh, kl, v16);

    // 4) attention (Q128, pipelined) -> fp16
    attn5<<<dim3(NHEAD, SEQ / 128), 512, AT5_SMEM>>>(qh, ql, kh, kl, v16, at16);

    // 5) h = attn @ W_out^T + x  (fp32 out)
    gemm_h<<<dim3(DMOD / 128, SEQ / 128), 256, GH_SMEM>>>(
        at16, DMOD, Wo16, DMOD, h, DMOD, x, DMOD);

    // 6) hn = LN(h) -> fp16
    ln_kernel<<<SEQ, 256>>>(h, hn16);

    // 7) g = hn @ W_ffp^T  (fp16 out)
    gemm_h16<<<dim3(DMLP / 128, SEQ / 128), 256, GH16_SMEM>>>(
        hn16, DMOD, Wp16, DMOD, g16, DMLP, DMOD);

    // 8) mlp = silu(g2)*g1 -> fp16
    swiglu_kernel<<<(SEQ * (DMLP / 2) + 255) / 256, 256>>>(g16, mlp16);

    // 9) out = mlp @ W_ffo^T + h  (fp32 out)
    gemm_h<<<dim3(DMOD / 128, SEQ / 128), 256, GH_SMEM>>>(
        mlp16, DMLP / 2, Wf16, DMLP / 2, out, DMOD, h, DMLP / 2);
}

// round 17
// speedup vs baseline: 1.1572x; 1.0960x over previous
#include <cuda_runtime.h>
#include <cuda_fp16.h>
#include <mma.h>
#include <math.h>
#include <cstdint>

using namespace nvcuda;

#define SEQ   2048
#define DMOD  1024
#define NHEAD 16
#define HDIM  64
#define DMLP  8192

// ---------------- scratch -----------------------------------------------------
__device__ float  g_qkv [SEQ * 3 * DMOD];
__device__ float  g_h   [SEQ * DMOD];
__device__ __half g_xn16 [SEQ * DMOD];
__device__ __half g_at16 [SEQ * DMOD];
__device__ __half g_hn16 [SEQ * DMOD];
__device__ __half g_g16 [SEQ * DMLP];
__device__ __half g_mlp16[SEQ * (DMLP / 2)];
__device__ __half g_Wa16[3 * DMOD * DMOD];
__device__ __half g_Wo16[DMOD * DMOD];
__device__ __half g_Wp16[DMLP * DMOD];
__device__ __half g_Wf16[DMOD * DMLP / 2];
// head-major RoPE'd q/k/v, fp16:  [h][l][64]
__device__ __half g_q16[SEQ * DMOD];
__device__ __half g_k16[SEQ * DMOD];
__device__ __half g_v16[SEQ * DMOD];

__device__ __forceinline__ void cp16h(__half* dst, const __half* src) {
    uint32_t s = (uint32_t)__cvta_generic_to_shared(dst);
    asm volatile("cp.async.cg.shared.global [%0], [%1], 16;\n" :: "r"(s), "l"(src));
}

// ---------------- fused fp32 -> fp16 convert for all 4 weights -----------------
__global__ void __launch_bounds__(256) cvt_all(
    const float* __restrict__ s0, __half* __restrict__ d0, int n0,
    const float* __restrict__ s1, __half* __restrict__ d1, int n1,
    const float* __restrict__ s2, __half* __restrict__ d2, int n2,
    const float* __restrict__ s3, __half* __restrict__ d3, int n3)
{
    long i = ((long)blockIdx.x * 256 + threadIdx.x) * 8;
    const float* s; __half* d; long off = i;
    if (off < n0)              { s = s0; d = d0; }
    else if ((off -= n0) < n1) { s = s1; d = d1; }
    else if ((off -= n1) < n2) { s = s2; d = d2; }
    else if ((off -= n2) < n3) { s = s3; d = d3; }
    else return;
    float4 v0 = *(const float4*)(s + off);
    float4 v1 = *(const float4*)(s + off + 4);
    float a[8] = {v0.x, v0.y, v0.z, v0.w, v1.x, v1.y, v1.z, v1.w};
    __align__(16) __half hh[8];
    #pragma unroll
    for (int e = 0; e < 8; e++) hh[e] = __float2half_rn(a[e]);
    *(uint4*)(d + off) = *(uint4*)hh;
}

// ---------------- LayerNorm -> fp16 ---------------------------------------------
__global__ void __launch_bounds__(256) ln_kernel(const float* __restrict__ x,
                                                 __half* __restrict__ y) {
    __shared__ float row[DMOD];
    __shared__ float red[256];
    const int r   = blockIdx.x;
    const int tid = threadIdx.x;
    const float* xr = x + (long)r * DMOD;

    float s = 0.f;
    #pragma unroll
    for (int i = 0; i < 4; i++) {
        float v = xr[tid + i * 256];
        row[tid + i * 256] = v;
        s += v;
    }
    red[tid] = s; __syncthreads();
    #pragma unroll
    for (int off = 128; off > 0; off >>= 1) {
        if (tid < off) red[tid] += red[tid + off];
        __syncthreads();
    }
    const float mu = red[0] * (1.f / DMOD);
    __syncthreads();

    float ss = 0.f;
    #pragma unroll
    for (int i = 0; i < 4; i++) {
        float d = row[tid + i * 256] - mu;
        ss += d * d;
    }
    red[tid] = ss; __syncthreads();
    #pragma unroll
    for (int off = 128; off > 0; off >>= 1) {
        if (tid < off) red[tid] += red[tid + off];
        __syncthreads();
    }
    const float inv = rsqrtf(red[0] * (1.f / DMOD) + 1e-5f);

    __half* yr = y + (long)r * DMOD;
    #pragma unroll
    for (int i = 0; i < 4; i++) {
        int c = tid + i * 256;
        yr[c] = __float2half_rn((row[c] - mu) * inv);
    }
}

// ---------------- common GEMM pieces --------------------------------------------
#define GBK   32
#define PADK  40
#define CSTR  132
#define GH_SMEM   (2 * 2 * 128 * PADK * (int)sizeof(__half))   // 40960 B
#define GH16_SMEM (128 * CSTR * (int)sizeof(float))            // 67584 B

#define GEMM_PROLOG_BODY                                                        \
    const int tid  = threadIdx.x;                                               \
    const int m0   = blockIdx.y * 128;                                          \
    const int n0   = blockIdx.x * 128;                                          \
    const int warp = tid >> 5;                                                  \
    const int wm0  = (warp & 3) * 32;                                           \
    const int wn0  = (warp >> 2) * 64;

#define GH_LOAD(ST, K0)                                                        \
do {                                                                           \
    __half* sb = smh + (ST) * (2 * 128 * PADK);                                \
    _Pragma("unroll")                                                          \
    for (int t = 0; t < 4; t++) {                                              \
        int c   = tid + t * 256;                                               \
        int arr = c >> 9;                                                      \
        int rem = c & 511;                                                     \
        int row = rem >> 2;                                                    \
        int col = (rem & 3) * 8;                                               \
        const __half* src = arr ? Bbase + (long)row * ldb + (K0) + col         \
                                : Abase + (long)row * lda + (K0) + col;        \
        cp16h(sb + arr * (128 * PADK) + row * PADK + col, src);                \
    }                                                                          \
    asm volatile("cp.async.commit_group;\n" ::);                               \
} while (0)

#define GEMM_MAINLOOP                                                           \
    const int nk = K / GBK;                                                     \
    GH_LOAD(0, 0);                                                              \
    for (int ks = 0; ks < nk; ks++) {                                           \
        asm volatile("cp.async.wait_group 0;\n" ::);                            \
        __syncthreads();                                                        \
        if (ks + 1 < nk) GH_LOAD((ks + 1) & 1, (ks + 1) * GBK);                 \
        __half* sb = smh + (ks & 1) * (2 * 128 * PADK);                         \
        __half* sA = sb;                                                        \
        __half* sB = sb + 128 * PADK;                                           \
        _Pragma("unroll")                                                       \
        for (int k16 = 0; k16 < GBK; k16 += 16) {                               \
            wmma::fragment<wmma::matrix_a, 16, 16, 16, __half,                  \
                           wmma::row_major> af[2];                              \
            _Pragma("unroll")                                                   \
            for (int i = 0; i < 2; i++)                                         \
                wmma::load_matrix_sync(af[i],                                   \
                    sA + (wm0 + 16 * i) * PADK + k16, PADK);                    \
            _Pragma("unroll")                                                   \
            for (int j = 0; j < 4; j++) {                                       \
                wmma::fragment<wmma::matrix_b, 16, 16, 16, __half,              \
                               wmma::col_major> bfr;                            \
                wmma::load_matrix_sync(bfr,                                     \
                    sB + (wn0 + 16 * j) * PADK + k16, PADK);                    \
                _Pragma("unroll")                                               \
                for (int i = 0; i < 2; i++)                                     \
                    wmma::mma_sync(acc[i][j], af[i], bfr, acc[i][j]);           \
            }                                                                   \
        }                                                                       \
    }

// ---------------- GEMM -> fp32 C (+Res) ------------------------------------------
__global__ void __launch_bounds__(256, 2) gemm_h(
    const __half* __restrict__ A, int lda,
    const __half* __restrict__ B, int ldb,
    float* __restrict__ C, int ldc, const float* __restrict__ Res, int K)
{
    extern __shared__ __half smh[];
    GEMM_PROLOG_BODY
    wmma::fragment<wmma::accumulator, 16, 16, 16, float> acc[2][4];
    #pragma unroll
    for (int i = 0; i < 2; i++)
        #pragma unroll
        for (int j = 0; j < 4; j++) {
            if (Res) {
                const float* rp = Res + (long)(m0 + wm0 + 16 * i) * ldc
                                      + n0 + wn0 + 16 * j;
                wmma::load_matrix_sync(acc[i][j], rp, ldc, wmma::mem_row_major);
            } else {
                wmma::fill_fragment(acc[i][j], 0.f);
            }
        }
    const __half* Abase = A + (long)m0 * lda;
    const __half* Bbase = B + (long)n0 * ldb;
    GEMM_MAINLOOP
    #pragma unroll
    for (int i = 0; i < 2; i++)
        #pragma unroll
        for (int j = 0; j < 4; j++) {
            float* cp = C + (long)(m0 + wm0 + 16 * i) * ldc + n0 + wn0 + 16 * j;
            wmma::store_matrix_sync(cp, acc[i][j], ldc, wmma::mem_row_major);
        }
}

// ---------------- GEMM -> fp16 C (smem-staged epilogue) --------------------------
__global__ void __launch_bounds__(256, 2) gemm_h16(
    const __half* __restrict__ A, int lda,
    const __half* __restrict__ B, int ldb,
    __half* __restrict__ C, int ldc, int K)
{
    extern __shared__ __half smh[];
    GEMM_PROLOG_BODY
    wmma::fragment<wmma::accumulator, 16, 16, 16, float> acc[2][4];
    #pragma unroll
    for (int i = 0; i < 2; i++)
        #pragma unroll
        for (int j = 0; j < 4; j++) wmma::fill_fragment(acc[i][j], 0.f);
    const __half* Abase = A + (long)m0 * lda;
    const __half* Bbase = B + (long)n0 * ldb;
    GEMM_MAINLOOP

    __syncthreads();
    float* Ct = (float*)smh;
    #pragma unroll
    for (int i = 0; i < 2; i++)
        #pragma unroll
        for (int j = 0; j < 4; j++)
            wmma::store_matrix_sync(Ct + (wm0 + 16 * i) * CSTR + wn0 + 16 * j,
                                    acc[i][j], CSTR, wmma::mem_row_major);
    __syncthreads();
    #pragma unroll
    for (int t = 0; t < 16; t++) {
        int c = (tid + t * 256) * 4;
        int row = c >> 7, col = c & 127;
        float4 v = *(float4*)(Ct + row * CSTR + col);
        __align__(8) __half hh[4] = {__float2half_rn(v.x), __float2half_rn(v.y),
                                     __float2half_rn(v.z), __float2half_rn(v.w)};
        *(uint2*)(C + (long)(m0 + row) * ldc + n0 + col) = *(uint2*)hh;
    }
}

// ---------------- RoPE + head-major split: q,k,v -> fp16 ------------------------
__global__ void __launch_bounds__(256) rope_split(
    const float* __restrict__ qkv,
    __half* __restrict__ q16, __half* __restrict__ k16,
    __half* __restrict__ v16)
{
    const int idx = blockIdx.x * 256 + threadIdx.x;
    if (idx >= SEQ * NHEAD * 32) return;
    const int j = idx & 31;
    const int h = (idx >> 5) & (NHEAD - 1);
    const int l = idx >> 9;

    const float inv_freq = powf(10000.f, -(float)j / 32.f);
    const float ang = (float)l * inv_freq;
    float c, s;
    sincosf(ang, &s, &c);

    const float* qp = qkv + (long)l * (3 * DMOD) + h * HDIM + j;
    const float q1 = qp[0], q2 = qp[32];
    const float k1 = qp[DMOD], k2 = qp[DMOD + 32];
    const float v1 = qp[2 * DMOD], v2 = qp[2 * DMOD + 32];

    const long dst = ((long)h * SEQ + l) * HDIM + j;
    q16[dst]      = __float2half_rn((q1 * c - q2 * s) * 0.125f);
    q16[dst + 32] = __float2half_rn((q2 * c + q1 * s) * 0.125f);
    k16[dst]      = __float2half_rn(k1 * c - k2 * s);
    k16[dst + 32] = __float2half_rn(k2 * c + k1 * s);
    v16[dst]      = __float2half_rn(v1);
    v16[dst + 32] = __float2half_rn(v2);
}

// ---------------- Flash attention Q128, fp16 single-pass, register O ------------
#define QSTR 80
#define FSTR 68
#define KSTG (64 * QSTR)                   // halves per K or V tile
// smem: K/V stages 40960 | P 20480 | Sf x2 69632 = 131072 B
#define AT6_SMEM (2 * 2 * KSTG * 2 + 128 * QSTR * 2 + 2 * 128 * FSTR * 4)

__global__ void __launch_bounds__(512, 1) attn6(
    const __half* __restrict__ Q16, const __half* __restrict__ K16,
    const __half* __restrict__ V16,
    __half* __restrict__ out)
{
    extern __shared__ char smraw[];
    __half* sKV = (__half*)smraw;                        // [st][K|V][KSTG]
    __half* P   = (__half*)(smraw + 2 * 2 * KSTG * 2);   // 128 x QSTR
    float*  SfB = (float*)(smraw + 2 * 2 * KSTG * 2 + 128 * QSTR * 2);

    const int h     = blockIdx.x;
    const int qb    = (int)gridDim.y - 1 - (int)blockIdx.y;
    const int tid   = threadIdx.x;
    const int warp  = tid >> 5;
    const int qbase = qb * 128;
    const int rt    = warp >> 1;
    const int chalf = (warp & 1) * 32;

    // ---- stage Q (128 rows) through the P buffer, read fragments once
    const long qoff = ((long)h * SEQ + qbase) * HDIM;
    #pragma unroll
    for (int t = 0; t < 2; t++) {
        int c = tid + t * 512;
        int row = c >> 3, ch = (c & 7) * 8;
        cp16h(P + row * QSTR + ch, Q16 + qoff + row * HDIM + ch);
    }
    asm volatile("cp.async.commit_group;\n" ::);
    asm volatile("cp.async.wait_group 0;\n" ::);
    __syncthreads();

    wmma::fragment<wmma::matrix_a, 16, 16, 16, __half, wmma::row_major> qf[4];
    #pragma unroll
    for (int ks = 0; ks < 4; ks++)
        wmma::load_matrix_sync(qf[ks], P + rt * 16 * QSTR + ks * 16, QSTR);
    __syncthreads();                                     // P reusable

    #define AT_LOAD(ST, KB)                                                     \
    do {                                                                        \
        const long koff = ((long)h * SEQ + (KB) * 64) * HDIM;                   \
        __half* dK = sKV + (ST) * 2 * KSTG;                                     \
        __half* dV = dK + KSTG;                                                 \
        int row = tid >> 3, ch = (tid & 7) * 8;                                 \
        cp16h(dK + row * QSTR + ch, K16 + koff + row * HDIM + ch);              \
        cp16h(dV + row * QSTR + ch, V16 + koff + row * HDIM + ch);              \
        asm volatile("cp.async.commit_group;\n" ::);                            \
    } while (0)

    #define QK_MMA(KST, SFDST)                                                  \
    do {                                                                        \
        __half* xK = sKV + (KST) * 2 * KSTG;                                    \
        _Pragma("unroll")                                                       \
        for (int ct = 0; ct < 2; ct++) {                                        \
            const int col0 = chalf + ct * 16;                                   \
            wmma::fragment<wmma::accumulator, 16, 16, 16, float> acc;           \
            wmma::fill_fragment(acc, 0.f);                                      \
            _Pragma("unroll")                                                   \
            for (int ks = 0; ks < 4; ks++) {                                    \
                wmma::fragment<wmma::matrix_b, 16, 16, 16, __half,              \
                               wmma::col_major> bfr;                            \
                wmma::load_matrix_sync(bfr, xK + col0 * QSTR + ks * 16, QSTR);  \
                wmma::mma_sync(acc, qf[ks], bfr, acc);                          \
            }                                                                   \
            wmma::store_matrix_sync((SFDST) + rt * 16 * FSTR + col0, acc, FSTR, \
                                    wmma::mem_row_major);                       \
        }                                                                       \
    } while (0)

    const int r  = tid >> 2;
    const int cs = (tid & 3) * 16;
    float mrow = -1e30f, lsum = 0.f, alpha = 0.f;
    float of[16];
    #pragma unroll
    for (int j = 0; j < 16; j++) of[j] = 0.f;

    const int nkb = (qbase + 128) >> 6;
    AT_LOAD(0, 0);
    if (nkb > 1) AT_LOAD(1, 1);
    asm volatile("cp.async.wait_group 0;\n" ::);
    __syncthreads();

    QK_MMA(0, SfB);                                      // S(0) -> Sf[0]
    __syncthreads();

    for (int kb = 0; kb < nkb; kb++) {
        const int st = kb & 1;
        float*  Sc = SfB + st * (128 * FSTR);            // S(kb) then T(kb)
        float*  Sn = SfB + (st ^ 1) * (128 * FSTR);
        __half* cV = sKV + st * 2 * KSTG + KSTG;

        // ---- softmax on S(kb); write P (fp16)
        const int kbase = kb * 64;
        float s[16];
        #pragma unroll
        for (int j = 0; j < 16; j++) s[j] = Sc[r * FSTR + cs + j];
        if (kbase + 64 > qbase) {
            #pragma unroll
            for (int j = 0; j < 16; j++)
                if (kbase + cs + j > qbase + r) s[j] = -1e30f;
        }
        float mloc = s[0];
        #pragma unroll
        for (int j = 1; j < 16; j++) mloc = fmaxf(mloc, s[j]);
        mloc = fmaxf(mloc, __shfl_xor_sync(0xffffffffu, mloc, 1));
        mloc = fmaxf(mloc, __shfl_xor_sync(0xffffffffu, mloc, 2));
        const float mnew = fmaxf(mrow, mloc);
        alpha = __expf(mrow - mnew);

        float ps = 0.f;
        #pragma unroll
        for (int j = 0; j < 16; j++) {
            float p = __expf(s[j] - mnew);
            ps += p;
            P[r * QSTR + cs + j] = __float2half_rn(p);
        }
        ps += __shfl_xor_sync(0xffffffffu, ps, 1);
        ps += __shfl_xor_sync(0xffffffffu, ps, 2);
        lsum = lsum * alpha + ps;
        mrow = mnew;

        asm volatile("cp.async.wait_group 0;\n" ::);
        __syncthreads();

        // ---- fused mma region: PV(kb) -> Sc  AND  QK(kb+1) -> Sn
        #pragma unroll
        for (int ct = 0; ct < 2; ct++) {
            const int col0 = chalf + ct * 16;
            wmma::fragment<wmma::accumulator, 16, 16, 16, float> acc;
            wmma::fill_fragment(acc, 0.f);
            #pragma unroll
            for (int js = 0; js < 4; js++) {
                wmma::fragment<wmma::matrix_a, 16, 16, 16, __half, wmma::row_major> pf;
                wmma::load_matrix_sync(pf, P + rt * 16 * QSTR + js * 16, QSTR);
                wmma::fragment<wmma::matrix_b, 16, 16, 16, __half, wmma::row_major> vf;
                wmma::load_matrix_sync(vf, cV + js * 16 * QSTR + col0, QSTR);
                wmma::mma_sync(acc, pf, vf, acc);
            }
            wmma::store_matrix_sync(Sc + rt * 16 * FSTR + col0, acc, FSTR,
                                    wmma::mem_row_major);
        }
        if (kb + 1 < nkb) QK_MMA(st ^ 1, Sn);
        __syncthreads();

        // ---- O (registers) = alpha*O + T ; prefetch K/V(kb+2)
        #pragma unroll
        for (int j = 0; j < 16; j++)
            of[j] = of[j] * alpha + Sc[r * FSTR + cs + j];
        if (kb + 2 < nkb) AT_LOAD(st, kb + 2);
    }

    const float invl = 1.f / lsum;
    __half* orow = out + (long)(qbase + r) * DMOD + h * HDIM + cs;
    #pragma unroll
    for (int j = 0; j < 16; j++)
        orow[j] = __float2half_rn(of[j] * invl);
}

// ---------------- SwiGLU (fp16 in) -> fp16 ----------------------------------------
__global__ void __launch_bounds__(256) swiglu_kernel(const __half* __restrict__ g,
                                                     __half* __restrict__ o) {
    const int idx = blockIdx.x * 256 + threadIdx.x;
    if (idx >= SEQ * (DMLP / 2)) return;
    const int rw = idx >> 12;
    const int c  = idx & 4095;
    const float x1 = __half2float(g[(long)rw * DMLP + c]);
    const float x2 = __half2float(g[(long)rw * DMLP + (DMLP / 2) + c]);
    const float sig = 1.f / (1.f + __expf(-x2));
    o[idx] = __float2half_rn(x2 * sig * x1);
}

// ---------------- launch -----------------------------------------------------------
extern "C" void kernel_launch(void* const* d_in, const int* in_sizes, int n_in,
                              void* d_out, int out_size) {
    const float* x      = (const float*)d_in[0];
    const float* W_attn = (const float*)d_in[2];
    const float* W_out  = (const float*)d_in[3];
    const float* W_ffp  = (const float*)d_in[4];
    const float* W_ffo  = (const float*)d_in[5];
    float* out = (float*)d_out;

    float *qkv, *h;
    __half *xn16, *at16, *hn16, *g16, *mlp16, *Wa16, *Wo16, *Wp16, *Wf16;
    __half *q16, *k16, *v16;
    cudaGetSymbolAddress((void**)&qkv,  g_qkv);
    cudaGetSymbolAddress((void**)&h,    g_h);
    cudaGetSymbolAddress((void**)&xn16, g_xn16);
    cudaGetSymbolAddress((void**)&at16, g_at16);
    cudaGetSymbolAddress((void**)&hn16, g_hn16);
    cudaGetSymbolAddress((void**)&g16,  g_g16);
    cudaGetSymbolAddress((void**)&mlp16,g_mlp16);
    cudaGetSymbolAddress((void**)&Wa16, g_Wa16);
    cudaGetSymbolAddress((void**)&Wo16, g_Wo16);
    cudaGetSymbolAddress((void**)&Wp16, g_Wp16);
    cudaGetSymbolAddress((void**)&Wf16, g_Wf16);
    cudaGetSymbolAddress((void**)&q16, g_q16);
    cudaGetSymbolAddress((void**)&k16, g_k16);
    cudaGetSymbolAddress((void**)&v16, g_v16);

    cudaFuncSetAttribute(attn6,
                         cudaFuncAttributeMaxDynamicSharedMemorySize, AT6_SMEM);
    cudaFuncSetAttribute(gemm_h,
                         cudaFuncAttributeMaxDynamicSharedMemorySize, GH_SMEM);
    cudaFuncSetAttribute(gemm_h16,
                         cudaFuncAttributeMaxDynamicSharedMemorySize, GH16_SMEM);

    // fused weight converts
    {
        int n0 = 3 * DMOD * DMOD, n1 = DMOD * DMOD,
            n2 = DMLP * DMOD,     n3 = DMOD * DMLP / 2;
        long total = (long)n0 + n1 + n2 + n3;
        cvt_all<<<(int)(total / 8 / 256), 256>>>(W_attn, Wa16, n0, W_out, Wo16, n1,
                                                 W_ffp, Wp16, n2, W_ffo, Wf16, n3);
    }

    // 1) xn = LN(x) -> fp16
    ln_kernel<<<SEQ, 256>>>(x, xn16);

    // 2) qkv = xn @ W_attn^T  (fp32 out)
    gemm_h<<<dim3(3 * DMOD / 128, SEQ / 128), 256, GH_SMEM>>>(
        xn16, DMOD, Wa16, DMOD, qkv, 3 * DMOD, nullptr, DMOD);

    // 3) RoPE + head-major split -> fp16
    rope_split<<<(SEQ * NHEAD * 32 + 255) / 256, 256>>>(qkv, q16, k16, v16);

    // 4) attention (Q128, fp16 single-pass, pipelined) -> fp16
    attn6<<<dim3(NHEAD, SEQ / 128), 512, AT6_SMEM>>>(q16, k16, v16, at16);

    // 5) h = attn @ W_out^T + x  (fp32 out)
    gemm_h<<<dim3(DMOD / 128, SEQ / 128), 256, GH_SMEM>>>(
        at16, DMOD, Wo16, DMOD, h, DMOD, x, DMOD);

    // 6) hn = LN(h) -> fp16
    ln_kernel<<<SEQ, 256>>>(h, hn16);

    // 7) g = hn @ W_ffp^T  (fp16 out)
    gemm_h16<<<dim3(DMLP / 128, SEQ / 128), 256, GH16_SMEM>>>(
        hn16, DMOD, Wp16, DMOD, g16, DMLP, DMOD);

    // 8) mlp = silu(g2)*g1 -> fp16
    swiglu_kernel<<<(SEQ * (DMLP / 2) + 255) / 256, 256>>>(g16, mlp16);

    // 9) out = mlp @ W_ffo^T + h  (fp32 out)
    gemm_h<<<dim3(DMOD / 128, SEQ / 128), 256, GH_SMEM>>>(
        mlp16, DMLP / 2, Wf16, DMLP / 2, out, DMOD, h, DMLP / 2);
}